// round 2
// baseline (speedup 1.0000x reference)
#include <cuda_runtime.h>
#include <cstdint>

// ---------------------------------------------------------------------------
// LightGCN encoder:
//   deg = in-degree(dst); dis = deg>0 ? rsqrt(deg) : 0
//   h_{k+1}[n] = sum_{e: dst=n} dis[src]*dis[n] * h_k[src]
//   out = ((x + h1 + h2 + h3)/4) @ W + b
//
// CSR build (edges bucketed by dst) per launch, pull-based propagation
// (no float atomics), fused running-total, smem GEMM epilogue.
// edge_index dtype (int32 vs int64) detected on-device.
// ---------------------------------------------------------------------------

#define NMAX 100000
#define EMAX 625024
#define DFEAT 128
#define DOUT 64

__device__ int   g_is64;
__device__ int   g_deg[NMAX];
__device__ float g_dis[NMAX];
__device__ int   g_rowstart[NMAX + 1];
__device__ int   g_cursor[NMAX];
__device__ int   g_src_sorted[EMAX];
__device__ float g_w_sorted[EMAX];
__device__ __align__(16) float g_hA[(size_t)NMAX * DFEAT];
__device__ __align__(16) float g_hB[(size_t)NMAX * DFEAT];
__device__ __align__(16) float g_total[(size_t)NMAX * DFEAT];

// ---------------------------------------------------------------------------
// Detect whether edge_index is int64 or int32.
// Reads first 1024 int64 words (8 KB) — in-bounds for either dtype
// (buffer is >= 5 MB). If genuinely int64, every value is in [0, n).
// If int32, the high half of each word is a second (almost surely
// nonzero) index, making the int64 value >= 2^32.
__global__ void k_detect(const long long* __restrict__ ei, int n) {
    __shared__ int ok;
    if (threadIdx.x == 0) ok = 1;
    __syncthreads();
    long long v = ei[threadIdx.x];           // 1024 threads
    if (v < 0 || v >= (long long)n) atomicAnd(&ok, 0);
    __syncthreads();
    if (threadIdx.x == 0) g_is64 = ok;
}

__global__ void k_zero_deg(int n) {
    int i = blockIdx.x * blockDim.x + threadIdx.x;
    if (i < n) g_deg[i] = 0;
}

__global__ void k_deg(const void* __restrict__ eiv, int e) {
    int i = blockIdx.x * blockDim.x + threadIdx.x;
    if (i >= e) return;
    int d;
    if (g_is64) d = (int)((const long long*)eiv)[(size_t)e + i];
    else        d = ((const int*)eiv)[(size_t)e + i];
    atomicAdd(&g_deg[d], 1);
}

__global__ void k_dis(int n) {
    int i = blockIdx.x * blockDim.x + threadIdx.x;
    if (i < n) {
        int d = g_deg[i];
        g_dis[i] = (d > 0) ? rsqrtf((float)d) : 0.0f;
    }
}

// Single-block exclusive scan of g_deg -> g_rowstart (+ cursor copy).
__global__ void k_scan(int n) {
    __shared__ int s[1024];
    int t = threadIdx.x;
    int chunk = (n + 1023) / 1024;
    int beg = min(t * chunk, n);
    int end = min(beg + chunk, n);

    int sum = 0;
    for (int i = beg; i < end; i++) sum += g_deg[i];
    s[t] = sum;
    __syncthreads();

    for (int o = 1; o < 1024; o <<= 1) {
        int v = 0;
        if (t >= o) v = s[t - o];
        __syncthreads();
        if (t >= o) s[t] += v;
        __syncthreads();
    }

    int run = (t > 0) ? s[t - 1] : 0;
    for (int i = beg; i < end; i++) {
        g_rowstart[i] = run;
        g_cursor[i]   = run;
        run += g_deg[i];
    }
    if (t == 1023) g_rowstart[n] = s[1023];
}

__global__ void k_fill(const void* __restrict__ eiv, int e) {
    int i = blockIdx.x * blockDim.x + threadIdx.x;
    if (i >= e) return;
    int s, d;
    if (g_is64) {
        s = (int)((const long long*)eiv)[i];
        d = (int)((const long long*)eiv)[(size_t)e + i];
    } else {
        s = ((const int*)eiv)[i];
        d = ((const int*)eiv)[(size_t)e + i];
    }
    int p = atomicAdd(&g_cursor[d], 1);
    g_src_sorted[p] = s;
    g_w_sorted[p]   = g_dis[s] * g_dis[d];
}

// One warp per node; each lane owns 4 consecutive features (float4).
// FIRST=1: total = x + acc; else total += acc.
template <int FIRST>
__global__ void k_layer(const float* __restrict__ hin,
                        float* __restrict__ hout,
                        const float* __restrict__ x,
                        int n) {
    int gw = (blockIdx.x * blockDim.x + threadIdx.x) >> 5;
    if (gw >= n) return;
    int lane = threadIdx.x & 31;

    int beg = g_rowstart[gw];
    int end = g_rowstart[gw + 1];

    float4 acc = make_float4(0.f, 0.f, 0.f, 0.f);
    for (int e = beg; e < end; e++) {
        int   s = g_src_sorted[e];        // broadcast
        float w = g_w_sorted[e];          // broadcast
        float4 v = *(const float4*)(hin + (size_t)s * DFEAT + lane * 4);
        acc.x += w * v.x;
        acc.y += w * v.y;
        acc.z += w * v.z;
        acc.w += w * v.w;
    }

    size_t off = (size_t)gw * DFEAT + lane * 4;
    *(float4*)(hout + off) = acc;

    float4 t;
    if (FIRST) {
        float4 xr = *(const float4*)(x + off);
        t = make_float4(xr.x + acc.x, xr.y + acc.y, xr.z + acc.z, xr.w + acc.w);
    } else {
        float4 tr = *(const float4*)(g_total + off);
        t = make_float4(tr.x + acc.x, tr.y + acc.y, tr.z + acc.z, tr.w + acc.w);
    }
    *(float4*)(g_total + off) = t;
}

// out[n,64] = (total * 0.25) @ W[128,64] + b.
__global__ void k_gemm(const float* __restrict__ W,
                       const float* __restrict__ b,
                       float* __restrict__ out,
                       int n) {
    __shared__ float Ws[DFEAT * DOUT];   // 32 KB
    __shared__ float bs[DOUT];
    __shared__ float rs[4][DFEAT];

    int tid = threadIdx.x;
    for (int i = tid; i < DFEAT * DOUT; i += 256) Ws[i] = W[i] * 0.25f;
    if (tid < DOUT) bs[tid] = b[tid];
    __syncthreads();

    int g = tid >> 6;
    int c = tid & 63;
    int base = blockIdx.x * 16;

    for (int it = 0; it < 4; it++) {
        int row0 = base + it * 4;
        for (int i = tid; i < 4 * DFEAT; i += 256) {
            int r = row0 + (i >> 7);
            rs[i >> 7][i & 127] = (r < n) ? g_total[(size_t)r * DFEAT + (i & 127)] : 0.f;
        }
        __syncthreads();

        float sum = 0.f;
        #pragma unroll 16
        for (int k = 0; k < DFEAT; k++)
            sum += rs[g][k] * Ws[k * DOUT + c];

        int row = row0 + g;
        if (row < n)
            out[(size_t)row * DOUT + c] = sum + bs[c];
        __syncthreads();
    }
}

// ---------------------------------------------------------------------------

extern "C" void kernel_launch(void* const* d_in, const int* in_sizes, int n_in,
                              void* d_out, int out_size) {
    const float* x  = (const float*)d_in[0];   // [N,128]
    const float* W  = (const float*)d_in[1];   // [128,64]
    const float* b  = (const float*)d_in[2];   // [64]
    const void*  ei = d_in[3];                 // [2,E] int32 or int64
    float* out = (float*)d_out;

    int n = in_sizes[0] / DFEAT;
    int e = in_sizes[3] / 2;

    float *hA, *hB;
    cudaGetSymbolAddress((void**)&hA, g_hA);
    cudaGetSymbolAddress((void**)&hB, g_hB);

    const int TB = 256;
    int nb_n = (n + TB - 1) / TB;
    int nb_e = (e + TB - 1) / TB;

    k_detect<<<1, 1024>>>((const long long*)ei, n);
    k_zero_deg<<<nb_n, TB>>>(n);
    k_deg<<<nb_e, TB>>>(ei, e);
    k_dis<<<nb_n, TB>>>(n);
    k_scan<<<1, 1024>>>(n);
    k_fill<<<nb_e, TB>>>(ei, e);

    int lg = (n * 32 + TB - 1) / TB;
    k_layer<1><<<lg, TB>>>(x,  hA, x, n);
    k_layer<0><<<lg, TB>>>(hA, hB, nullptr, n);
    k_layer<0><<<lg, TB>>>(hB, hA, nullptr, n);

    int gb = (n + 15) / 16;
    k_gemm<<<gb, 256>>>(W, b, out, n);
}

// round 3
// speedup vs baseline: 1.2755x; 1.2755x over previous
#include <cuda_runtime.h>
#include <cstdint>

// ---------------------------------------------------------------------------
// LightGCN encoder, pull-based CSR propagation + register-tiled GEMM.
//   deg = in-degree(dst); dis = deg>0 ? rsqrt(deg) : 0
//   h_{k+1}[n] = sum_{e: dst=n} dis[src]*dis[dst] * h_k[src]
//   out = 0.25*(x + h1 + h2 + h3) @ W + b
// edge_index dtype (int32 vs int64) detected on-device.
// ---------------------------------------------------------------------------

#define NMAX 100000
#define EMAX 625024
#define DFEAT 128
#define DOUT 64
#define NBMAX 512   // >= ceil(NMAX/256)

__device__ int   g_is64;
__device__ int   g_deg[NMAX];
__device__ float g_dis[NMAX];
__device__ int   g_partial[NBMAX];
__device__ int   g_partofs[NBMAX];
__device__ int   g_rowstart[NMAX + 1];
__device__ int   g_cursor[NMAX];
__device__ int2  g_edge[EMAX];          // {src, bitcast(weight)}
__device__ __align__(16) float g_hA[(size_t)NMAX * DFEAT];
__device__ __align__(16) float g_hB[(size_t)NMAX * DFEAT];
__device__ __align__(16) float g_hC[(size_t)NMAX * DFEAT];

// ---------------------------------------------------------------------------
// dtype probe: 8 KB read is in-bounds either way; genuine int64 indices are
// all in [0,n), packed int32 pairs give values >= 2^32 almost surely.
__global__ void k_detect(const long long* __restrict__ ei, int n) {
    __shared__ int ok;
    if (threadIdx.x == 0) ok = 1;
    __syncthreads();
    long long v = ei[threadIdx.x];
    if (v < 0 || v >= (long long)n) atomicAnd(&ok, 0);
    __syncthreads();
    if (threadIdx.x == 0) g_is64 = ok;
}

__global__ void k_zero_deg(int n) {
    int i = blockIdx.x * blockDim.x + threadIdx.x;
    if (i < n) g_deg[i] = 0;
}

__global__ void k_deg(const void* __restrict__ eiv, int e) {
    int i = blockIdx.x * blockDim.x + threadIdx.x;
    if (i >= e) return;
    int d;
    if (g_is64) d = (int)((const long long*)eiv)[(size_t)e + i];
    else        d = ((const int*)eiv)[(size_t)e + i];
    atomicAdd(&g_deg[d], 1);
}

// block partial sums of deg (+ compute dis on the way)
__global__ void k_blocksum(int n) {
    __shared__ int s[256];
    int t = threadIdx.x;
    int i = blockIdx.x * 256 + t;
    int v = (i < n) ? g_deg[i] : 0;
    if (i < n) g_dis[i] = (v > 0) ? rsqrtf((float)v) : 0.0f;
    s[t] = v;
    __syncthreads();
    for (int o = 128; o > 0; o >>= 1) {
        if (t < o) s[t] += s[t + o];
        __syncthreads();
    }
    if (t == 0) g_partial[blockIdx.x] = s[0];
}

// scan the block partials (one block)
__global__ void k_scanpart(int nb, int n, int e) {
    __shared__ int s[NBMAX];
    int t = threadIdx.x;
    int v = (t < nb) ? g_partial[t] : 0;
    s[t] = v;
    __syncthreads();
    for (int o = 1; o < NBMAX; o <<= 1) {
        int u = 0;
        if (t >= o) u = s[t - o];
        __syncthreads();
        if (t >= o) s[t] += u;
        __syncthreads();
    }
    if (t < nb) g_partofs[t] = s[t] - v;
    if (t == 0) g_rowstart[n] = e;
}

// per-block exclusive rescan -> rowstart/cursor
__global__ void k_rowstart(int n) {
    __shared__ int s[256];
    int t = threadIdx.x;
    int i = blockIdx.x * 256 + t;
    int v = (i < n) ? g_deg[i] : 0;
    s[t] = v;
    __syncthreads();
    for (int o = 1; o < 256; o <<= 1) {
        int u = 0;
        if (t >= o) u = s[t - o];
        __syncthreads();
        if (t >= o) s[t] += u;
        __syncthreads();
    }
    if (i < n) {
        int r = g_partofs[blockIdx.x] + s[t] - v;
        g_rowstart[i] = r;
        g_cursor[i]   = r;
    }
}

__global__ void k_fill(const void* __restrict__ eiv, int e) {
    int i = blockIdx.x * blockDim.x + threadIdx.x;
    if (i >= e) return;
    int s, d;
    if (g_is64) {
        s = (int)((const long long*)eiv)[i];
        d = (int)((const long long*)eiv)[(size_t)e + i];
    } else {
        s = ((const int*)eiv)[i];
        d = ((const int*)eiv)[(size_t)e + i];
    }
    int p = atomicAdd(&g_cursor[d], 1);
    g_edge[p] = make_int2(s, __float_as_int(g_dis[s] * g_dis[d]));
}

// One warp per node; lane owns 4 consecutive features.
// Predicated 4-wide edge groups -> 4 gathers in flight per step.
__global__ void k_layer(const float* __restrict__ hin,
                        float* __restrict__ hout, int n) {
    int gw = (blockIdx.x * blockDim.x + threadIdx.x) >> 5;
    if (gw >= n) return;
    int lane = threadIdx.x & 31;

    int beg = g_rowstart[gw];
    int end = g_rowstart[gw + 1];

    float4 acc = make_float4(0.f, 0.f, 0.f, 0.f);
    int last = end - 1;
    for (int e = beg; e < end; e += 4) {
        int2 p0 = g_edge[e];
        int2 p1 = g_edge[min(e + 1, last)];
        int2 p2 = g_edge[min(e + 2, last)];
        int2 p3 = g_edge[min(e + 3, last)];
        float w0 = __int_as_float(p0.y);
        float w1 = (e + 1 <= last) ? __int_as_float(p1.y) : 0.f;
        float w2 = (e + 2 <= last) ? __int_as_float(p2.y) : 0.f;
        float w3 = (e + 3 <= last) ? __int_as_float(p3.y) : 0.f;
        float4 v0 = *((const float4*)(hin + (size_t)p0.x * DFEAT) + lane);
        float4 v1 = *((const float4*)(hin + (size_t)p1.x * DFEAT) + lane);
        float4 v2 = *((const float4*)(hin + (size_t)p2.x * DFEAT) + lane);
        float4 v3 = *((const float4*)(hin + (size_t)p3.x * DFEAT) + lane);
        acc.x += w0 * v0.x + w1 * v1.x + w2 * v2.x + w3 * v3.x;
        acc.y += w0 * v0.y + w1 * v1.y + w2 * v2.y + w3 * v3.y;
        acc.z += w0 * v0.z + w1 * v1.z + w2 * v2.z + w3 * v3.z;
        acc.w += w0 * v0.w + w1 * v1.w + w2 * v2.w + w3 * v3.w;
    }
    *((float4*)(hout + (size_t)gw * DFEAT) + lane) = acc;
}

// out[n,64] = 0.25*(x+hA+hB+hC) @ W + b
// BM=64, BN=64, BK=32, 256 threads, 4x4 micro-tile per thread.
__global__ void k_gemm(const float* __restrict__ x,
                       const float* __restrict__ W,
                       const float* __restrict__ b,
                       float* __restrict__ out, int n) {
    __shared__ float As[32][65];   // [k][row], padded
    __shared__ float Bs[32][64];   // [k][col]

    int tid = threadIdx.x;
    int row0 = blockIdx.x * 64;
    int ty = tid >> 4;             // 0..15 (row group)
    int tx = tid & 15;             // 0..15 (col group)

    float c[4][4];
    #pragma unroll
    for (int i = 0; i < 4; i++)
        #pragma unroll
        for (int j = 0; j < 4; j++) c[i][j] = 0.f;

    for (int k0 = 0; k0 < DFEAT; k0 += 32) {
        // A tile: fused total = 0.25*(x+hA+hB+hC), 64 rows x 32 k
        #pragma unroll
        for (int i = tid; i < 64 * 32; i += 256) {
            int r  = i >> 5;
            int kk = i & 31;
            int row = row0 + r;
            float v = 0.f;
            if (row < n) {
                size_t off = (size_t)row * DFEAT + k0 + kk;
                v = 0.25f * (x[off] + g_hA[off] + g_hB[off] + g_hC[off]);
            }
            As[kk][r] = v;
        }
        // B tile: 32 k x 64 cols
        #pragma unroll
        for (int i = tid; i < 32 * 64; i += 256) {
            int kk = i >> 6;
            int cc = i & 63;
            Bs[kk][cc] = W[(size_t)(k0 + kk) * DOUT + cc];
        }
        __syncthreads();

        #pragma unroll
        for (int kk = 0; kk < 32; kk++) {
            float a[4], bb[4];
            #pragma unroll
            for (int i = 0; i < 4; i++) a[i]  = As[kk][ty * 4 + i];
            #pragma unroll
            for (int j = 0; j < 4; j++) bb[j] = Bs[kk][tx * 4 + j];
            #pragma unroll
            for (int i = 0; i < 4; i++)
                #pragma unroll
                for (int j = 0; j < 4; j++)
                    c[i][j] += a[i] * bb[j];
        }
        __syncthreads();
    }

    float b0 = b[tx * 4 + 0], b1 = b[tx * 4 + 1];
    float b2 = b[tx * 4 + 2], b3 = b[tx * 4 + 3];
    #pragma unroll
    for (int i = 0; i < 4; i++) {
        int row = row0 + ty * 4 + i;
        if (row < n) {
            float4 v = make_float4(c[i][0] + b0, c[i][1] + b1,
                                   c[i][2] + b2, c[i][3] + b3);
            *(float4*)(out + (size_t)row * DOUT + tx * 4) = v;
        }
    }
}

// ---------------------------------------------------------------------------

extern "C" void kernel_launch(void* const* d_in, const int* in_sizes, int n_in,
                              void* d_out, int out_size) {
    const float* x  = (const float*)d_in[0];   // [N,128]
    const float* W  = (const float*)d_in[1];   // [128,64]
    const float* b  = (const float*)d_in[2];   // [64]
    const void*  ei = d_in[3];                 // [2,E]
    float* out = (float*)d_out;

    int n = in_sizes[0] / DFEAT;
    int e = in_sizes[3] / 2;

    float *hA, *hB, *hC;
    cudaGetSymbolAddress((void**)&hA, g_hA);
    cudaGetSymbolAddress((void**)&hB, g_hB);
    cudaGetSymbolAddress((void**)&hC, g_hC);

    const int TB = 256;
    int nb_n = (n + TB - 1) / TB;
    int nb_e = (e + TB - 1) / TB;

    k_detect<<<1, 1024>>>((const long long*)ei, n);
    k_zero_deg<<<nb_n, TB>>>(n);
    k_deg<<<nb_e, TB>>>(ei, e);
    k_blocksum<<<nb_n, TB>>>(n);
    k_scanpart<<<1, NBMAX>>>(nb_n, n, e);
    k_rowstart<<<nb_n, TB>>>(n);
    k_fill<<<nb_e, TB>>>(ei, e);

    int lg = (n * 32 + TB - 1) / TB;
    k_layer<<<lg, TB>>>(x,  hA, n);
    k_layer<<<lg, TB>>>(hA, hB, n);
    k_layer<<<lg, TB>>>(hB, hC, n);

    int gb = (n + 63) / 64;
    k_gemm<<<gb, 256>>>(x, W, b, out, n);
}

// round 4
// speedup vs baseline: 2.8730x; 2.2525x over previous
#include <cuda_runtime.h>
#include <cstdint>

// ---------------------------------------------------------------------------
// LightGCN encoder. Key identity: propagation S is linear over features and
// W acts on the feature dim, so  mean_k(S^k x) @ W = mean_k(S^k (x @ W)).
// Pipeline:
//   1. CSR build (edges bucketed by dst), edge weight dis[src]*dis[dst].
//   2. y0 = x @ (0.25*W)              [100k x 64]  (0.25 = mean folded in)
//   3. y1 = S y0, y2 = S y1           (gathers in d=64, L2-resident buffers)
//   4. out = y0+y1+y2+S y2 + b        (fused into layer 3)
// edge_index dtype (int32 vs int64) detected on-device.
// ---------------------------------------------------------------------------

#define NMAX 100000
#define EMAX 625024
#define DFEAT 128
#define DH 64
#define NBMAX 512   // >= ceil(NMAX/256)

__device__ int   g_is64;
__device__ int   g_deg[NMAX];
__device__ float g_dis[NMAX];
__device__ int   g_partial[NBMAX];
__device__ int   g_partofs[NBMAX];
__device__ int   g_rowstart[NMAX + 1];
__device__ int   g_cursor[NMAX];
__device__ int2  g_edge[EMAX];          // {src, bitcast(weight)}
__device__ __align__(16) float g_y0[(size_t)NMAX * DH];
__device__ __align__(16) float g_y1[(size_t)NMAX * DH];
__device__ __align__(16) float g_y2[(size_t)NMAX * DH];

// ---------------------------------------------------------------------------
// Fused: zero degree array + dtype probe (block 0).
// Probe reads 256 int64 (2 KB) — in-bounds under either dtype. Genuine int64
// indices are all in [0,n); packed int32 pairs give values >= 2^32 unless the
// odd-position index is exactly 0 (P ~ 1e-5 per probe, ~1e-1280 for all 256).
__global__ void k_init(const long long* __restrict__ ei, int n) {
    int i = blockIdx.x * blockDim.x + threadIdx.x;
    if (i < n) g_deg[i] = 0;
    if (blockIdx.x == 0) {
        long long v = ei[threadIdx.x];
        int bad = (v < 0 || v >= (long long)n) ? 1 : 0;
        int any = __syncthreads_or(bad);
        if (threadIdx.x == 0) g_is64 = !any;
    }
}

__global__ void k_deg(const void* __restrict__ eiv, int e) {
    int i = blockIdx.x * blockDim.x + threadIdx.x;
    if (i >= e) return;
    int d;
    if (g_is64) d = (int)((const long long*)eiv)[(size_t)e + i];
    else        d = ((const int*)eiv)[(size_t)e + i];
    atomicAdd(&g_deg[d], 1);
}

// block partial sums of deg (+ dis on the way)
__global__ void k_blocksum(int n) {
    __shared__ int s[256];
    int t = threadIdx.x;
    int i = blockIdx.x * 256 + t;
    int v = (i < n) ? g_deg[i] : 0;
    if (i < n) g_dis[i] = (v > 0) ? rsqrtf((float)v) : 0.0f;
    s[t] = v;
    __syncthreads();
    for (int o = 128; o > 0; o >>= 1) {
        if (t < o) s[t] += s[t + o];
        __syncthreads();
    }
    if (t == 0) g_partial[blockIdx.x] = s[0];
}

// y0 = x @ (0.25*W).  BM=64, BN=64(full), BK=32, 256 threads, 4x4 micro-tile.
// Launched 4th so ncu (-s/-c bounded) profiles a hot kernel.
__global__ void k_gemm_y(const float* __restrict__ x,
                         const float* __restrict__ W,
                         float* __restrict__ y0, int n) {
    __shared__ float As[32][65];
    __shared__ float Bs[32][64];

    int tid = threadIdx.x;
    int row0 = blockIdx.x * 64;
    int ty = tid >> 4;
    int tx = tid & 15;

    float c[4][4];
    #pragma unroll
    for (int i = 0; i < 4; i++)
        #pragma unroll
        for (int j = 0; j < 4; j++) c[i][j] = 0.f;

    for (int k0 = 0; k0 < DFEAT; k0 += 32) {
        #pragma unroll
        for (int j = 0; j < 2; j++) {           // A: 64 rows x 32 k, float4
            int idx = tid + j * 256;            // 0..511
            int r  = idx >> 3;
            int k4 = (idx & 7) * 4;
            float4 v = make_float4(0.f, 0.f, 0.f, 0.f);
            int row = row0 + r;
            if (row < n) v = *(const float4*)(x + (size_t)row * DFEAT + k0 + k4);
            As[k4 + 0][r] = v.x; As[k4 + 1][r] = v.y;
            As[k4 + 2][r] = v.z; As[k4 + 3][r] = v.w;
        }
        #pragma unroll
        for (int j = 0; j < 2; j++) {           // B: 32 k x 64 cols, float4, *0.25
            int idx = tid + j * 256;
            int kk = idx >> 4;
            int c4 = (idx & 15) * 4;
            float4 v = *(const float4*)(W + (size_t)(k0 + kk) * DH + c4);
            Bs[kk][c4 + 0] = 0.25f * v.x; Bs[kk][c4 + 1] = 0.25f * v.y;
            Bs[kk][c4 + 2] = 0.25f * v.z; Bs[kk][c4 + 3] = 0.25f * v.w;
        }
        __syncthreads();

        #pragma unroll
        for (int kk = 0; kk < 32; kk++) {
            float a[4], bb[4];
            #pragma unroll
            for (int i = 0; i < 4; i++) a[i]  = As[kk][ty * 4 + i];
            #pragma unroll
            for (int j = 0; j < 4; j++) bb[j] = Bs[kk][tx * 4 + j];
            #pragma unroll
            for (int i = 0; i < 4; i++)
                #pragma unroll
                for (int j = 0; j < 4; j++)
                    c[i][j] += a[i] * bb[j];
        }
        __syncthreads();
    }

    #pragma unroll
    for (int i = 0; i < 4; i++) {
        int row = row0 + ty * 4 + i;
        if (row < n)
            *(float4*)(y0 + (size_t)row * DH + tx * 4) =
                make_float4(c[i][0], c[i][1], c[i][2], c[i][3]);
    }
}

// scan block partials (one block)
__global__ void k_scanpart(int nb, int n, int e) {
    __shared__ int s[NBMAX];
    int t = threadIdx.x;
    int v = (t < nb) ? g_partial[t] : 0;
    s[t] = v;
    __syncthreads();
    for (int o = 1; o < NBMAX; o <<= 1) {
        int u = 0;
        if (t >= o) u = s[t - o];
        __syncthreads();
        if (t >= o) s[t] += u;
        __syncthreads();
    }
    if (t < nb) g_partofs[t] = s[t] - v;
    if (t == 0) g_rowstart[n] = e;
}

// per-block exclusive rescan -> rowstart/cursor
__global__ void k_rowstart(int n) {
    __shared__ int s[256];
    int t = threadIdx.x;
    int i = blockIdx.x * 256 + t;
    int v = (i < n) ? g_deg[i] : 0;
    s[t] = v;
    __syncthreads();
    for (int o = 1; o < 256; o <<= 1) {
        int u = 0;
        if (t >= o) u = s[t - o];
        __syncthreads();
        if (t >= o) s[t] += u;
        __syncthreads();
    }
    if (i < n) {
        int r = g_partofs[blockIdx.x] + s[t] - v;
        g_rowstart[i] = r;
        g_cursor[i]   = r;
    }
}

__global__ void k_fill(const void* __restrict__ eiv, int e) {
    int i = blockIdx.x * blockDim.x + threadIdx.x;
    if (i >= e) return;
    int s, d;
    if (g_is64) {
        s = (int)((const long long*)eiv)[i];
        d = (int)((const long long*)eiv)[(size_t)e + i];
    } else {
        s = ((const int*)eiv)[i];
        d = ((const int*)eiv)[(size_t)e + i];
    }
    int p = atomicAdd(&g_cursor[d], 1);
    g_edge[p] = make_int2(s, __float_as_int(g_dis[s] * g_dis[d]));
}

// One warp per node in d=64; each lane owns 2 features (float2).
// 8 gathers in flight -> typical node (deg ~6) finishes in ONE latency round.
// LAST=1 fuses: out = y0 + y1 + yin + acc + b.
template <int LAST>
__global__ void k_layer(const float* __restrict__ yin,
                        float* __restrict__ yout,
                        const float* __restrict__ y0,
                        const float* __restrict__ y1,
                        const float* __restrict__ bvec,
                        float* __restrict__ out, int n) {
    int gw = (blockIdx.x * blockDim.x + threadIdx.x) >> 5;
    if (gw >= n) return;
    int lane = threadIdx.x & 31;

    int beg = g_rowstart[gw];
    int end = g_rowstart[gw + 1];
    int last = end - 1;

    float accx = 0.f, accy = 0.f;
    for (int e = beg; e < end; e += 8) {
        int2  p[8];
        float w[8];
        #pragma unroll
        for (int j = 0; j < 8; j++) {
            p[j] = g_edge[min(e + j, last)];
            w[j] = (e + j <= last) ? __int_as_float(p[j].y) : 0.f;
        }
        float2 v[8];
        #pragma unroll
        for (int j = 0; j < 8; j++)
            v[j] = *(const float2*)(yin + (size_t)p[j].x * DH + lane * 2);
        #pragma unroll
        for (int j = 0; j < 8; j++) {
            accx += w[j] * v[j].x;
            accy += w[j] * v[j].y;
        }
    }

    size_t off = (size_t)gw * DH + lane * 2;
    if (LAST) {
        float2 a = *(const float2*)(y0 + off);
        float2 b = *(const float2*)(y1 + off);
        float2 c = *(const float2*)(yin + off);
        float2 bb = *(const float2*)(bvec + lane * 2);
        float2 o = make_float2(a.x + b.x + c.x + accx + bb.x,
                               a.y + b.y + c.y + accy + bb.y);
        *(float2*)(out + off) = o;
    } else {
        *(float2*)(yout + off) = make_float2(accx, accy);
    }
}

// ---------------------------------------------------------------------------

extern "C" void kernel_launch(void* const* d_in, const int* in_sizes, int n_in,
                              void* d_out, int out_size) {
    const float* x  = (const float*)d_in[0];   // [N,128]
    const float* W  = (const float*)d_in[1];   // [128,64]
    const float* b  = (const float*)d_in[2];   // [64]
    const void*  ei = d_in[3];                 // [2,E]
    float* out = (float*)d_out;

    int n = in_sizes[0] / DFEAT;
    int e = in_sizes[3] / 2;

    float *y0, *y1, *y2;
    cudaGetSymbolAddress((void**)&y0, g_y0);
    cudaGetSymbolAddress((void**)&y1, g_y1);
    cudaGetSymbolAddress((void**)&y2, g_y2);

    const int TB = 256;
    int nb_n = (n + TB - 1) / TB;
    int nb_e = (e + TB - 1) / TB;

    k_init<<<nb_n, TB>>>((const long long*)ei, n);   // 1
    k_deg<<<nb_e, TB>>>(ei, e);                      // 2
    k_blocksum<<<nb_n, TB>>>(n);                     // 3
    k_gemm_y<<<(n + 63) / 64, 256>>>(x, W, y0, n);   // 4  (profiled by ncu)
    k_scanpart<<<1, NBMAX>>>(nb_n, n, e);            // 5
    k_rowstart<<<nb_n, TB>>>(n);                     // 6
    k_fill<<<nb_e, TB>>>(ei, e);                     // 7

    int lg = (n * 32 + TB - 1) / TB;
    k_layer<0><<<lg, TB>>>(y0, y1, nullptr, nullptr, nullptr, nullptr, n); // 8
    k_layer<0><<<lg, TB>>>(y1, y2, nullptr, nullptr, nullptr, nullptr, n); // 9
    k_layer<1><<<lg, TB>>>(y2, nullptr, y0, y1, b, out, n);                // 10
}